// round 12
// baseline (speedup 1.0000x reference)
#include <cuda_runtime.h>
#include <math.h>

#define BB 16384
#define CC 8192
#define GRID 1184            // 148 SMs x 8 CTAs (regs=32, 256 thr) -> 1 wave, persistent

// ---------------- device scratch (no runtime allocation) ----------------
// d_first2/d_cnt are ZERO when idle; k_main's final block re-zeroes them for
// the next graph replay. d_first2[lab] = max over rows i with label lab of
// (BB - i)  =>  first occurrence = BB - d_first2[lab]; 0 = label absent.
__device__ int   d_first2[CC];
__device__ int   d_cnt[CC];
__device__ int   d_hist[64 * CC];      // per-256-row-block histograms -> excl. block prefix
__device__ int   d_start[BB];          // excl. scan of group sizes (keyed by first-occ row)
__device__ int   d_rank[BB];           // stable rank within 256-row block (same label)
__device__ int   d_lab[BB];            // normalized int32 labels
__device__ float d_loss[BB];           // per-row loss
__device__ unsigned int d_ticket;      // last-block election in k_main

// ================= k1: detect + convert + count + stable in-block rank =================
__global__ void __launch_bounds__(256) k1(const void* __restrict__ labels) {
    const int t = threadIdx.x, b = blockIdx.x;
    __shared__ unsigned short srun[CC];   // 16KB running block histogram
    __shared__ int s_is64;

    // label width detection: int64 (LE) => all odd 32-bit words zero.
    // p < 8192 keeps word index valid for the int32 case too.
    {
        const int* w = (const int*)labels;
        int p = (b & 31) * 256 + t;
        int any = __syncthreads_or(w[2 * p + 1] != 0);
        if (t == 0) s_is64 = !any;
    }
    for (int k = t; k < CC; k += 256) srun[k] = 0;
    __syncthreads();

    const int i = b * 256 + t;
    const int lab = s_is64 ? (int)((const long long*)labels)[i]
                           : ((const int*)labels)[i];
    d_lab[i] = lab;
    atomicMax(&d_first2[lab], BB - i);     // zero-init friendly "first occurrence"
    atomicAdd(&d_cnt[lab], 1);

    // stable in-block rank via warp-ordered phases (u16 smem, no atomics)
    const int l = t & 31, w = t >> 5;
    unsigned eq = 0u;
#pragma unroll
    for (int j = 0; j < 32; j++) {
        int lj = __shfl_sync(0xffffffffu, lab, j);
        eq |= (unsigned)(lj == lab) << j;
    }
    const int before  = __popc(eq & ((1u << l) - 1u));
    const int total   = __popc(eq);
    const bool is_last = (31 - __clz(eq)) == l;
    int rank = 0;
    for (int ph = 0; ph < 8; ph++) {
        if (w == ph) {
            rank = (int)srun[lab] + before;
            __syncwarp();
            if (is_last) srun[lab] = (unsigned short)((int)srun[lab] + total);
        }
        __syncthreads();
    }
    d_rank[i] = rank;
    for (int k = t; k < CC; k += 256) d_hist[b * CC + k] = (int)srun[k];
}

// ================= k2: coalesced hist prefix (blocks 0-7) + group scan (block 8) =================
__global__ void __launch_bounds__(1024) k2() {
    const int t = threadIdx.x, b = blockIdx.x;
    if (b < 8) {
        // in-place exclusive prefix along the 64-block axis, one thread per
        // label column: consecutive threads -> consecutive addresses (coalesced)
        const int c = b * 1024 + t;
        int run = 0;
#pragma unroll 4
        for (int k = 0; k < 64; k++) {
            int v = d_hist[k * CC + c];
            d_hist[k * CC + c] = run;
            run += v;
        }
    } else {
        // exclusive scan of group sizes keyed by first-occurrence row
        __shared__ int sums[1024];
        const int base = t * 16;
        int local[16];
        int acc = 0;
#pragma unroll
        for (int k = 0; k < 16; k++) {
            int r = base + k;
            int lab = d_lab[r];
            int gv = (BB - d_first2[lab] == r) ? d_cnt[lab] : 0;
            local[k] = acc;
            acc += gv;
        }
        sums[t] = acc;
        __syncthreads();
        for (int off = 1; off < 1024; off <<= 1) {
            int v = (t >= off) ? sums[t - off] : 0;
            __syncthreads();
            sums[t] += v;
            __syncthreads();
        }
        int offset = (t == 0) ? 0 : sums[t - 1];
#pragma unroll
        for (int k = 0; k < 16; k++) d_start[base + k] = offset + local[k];
    }
}

// ================= persistent main streaming kernel =================
// GRID blocks (one wave, 8/SM). Each block loops over rows strided by GRID:
// no wave transitions, one fence+ticket per block.
__global__ void __launch_bounds__(256) k_main(const float* __restrict__ logits,
                                              float* __restrict__ out,
                                              long long osz) {
    const int t = threadIdx.x;
    const long long nbig = (long long)BB * CC;
    const bool do_store = (osz >= nbig);
    const bool do_lab   = (osz >= nbig + BB);
    __shared__ float red[8];

    for (int row = blockIdx.x; row < BB; row += GRID) {
        const int lab = d_lab[row];
        const int dst = d_start[BB - d_first2[lab]]
                      + d_hist[(row >> 8) * CC + lab] + d_rank[row];
        const float4* __restrict__ src = (const float4*)(logits + (size_t)row * CC);
        float4* __restrict__ o4 = (float4*)(out + (size_t)dst * CC);

        const int tgt4 = lab >> 2, tsub = lab & 3;

        float s0 = 0.0f, s1 = 0.0f;
        float tval = 0.0f;
        bool have_t = false;

#pragma unroll
        for (int k = 0; k < 8; k++) {
            const int idx = k * 256 + t;
            float4 x = __ldcs(src + idx);
            if (idx == tgt4) {
                float vv = (tsub == 0) ? x.x : (tsub == 1) ? x.y
                         : (tsub == 2) ? x.z : x.w;
                float nv = (vv > 0.0f) ? (vv / 2.00001f - 0.2f) : (vv * 2.00001f - 0.2f);
                if (tsub == 0) x.x = nv; else if (tsub == 1) x.y = nv;
                else if (tsub == 2) x.z = nv; else x.w = nv;
                tval = nv; have_t = true;
            }
            if (do_store) __stcs(o4 + idx, x);
            s0 += __expf(x.x) + __expf(x.y);
            s1 += __expf(x.z) + __expf(x.w);
        }

        // block float-sum reduction
        float ws = s0 + s1;
#pragma unroll
        for (int o = 16; o; o >>= 1) ws += __shfl_xor_sync(0xffffffffu, ws, o);
        if ((t & 31) == 0) red[t >> 5] = ws;
        __syncthreads();
        if (t < 32) {
            float v = (t < 8) ? red[t] : 0.0f;
#pragma unroll
            for (int o = 4; o; o >>= 1) v += __shfl_xor_sync(0xffffffffu, v, o);
            if (t == 0) red[0] = v;
        }
        __syncthreads();
        const float s = red[0];
        __syncthreads();                       // red[] reused next iteration

        if (have_t) d_loss[row] = __logf(s) - tval;
        if (t == 0 && do_lab) out[(size_t)nbig + dst] = (float)lab;
    }

    // ---- last block: deterministic loss reduction + scratch reset for next replay ----
    __threadfence();                           // publish all d_loss/out writes
    __shared__ unsigned int s_last;
    __syncthreads();
    if (t == 0) s_last = atomicAdd(&d_ticket, 1u);
    __syncthreads();
    if (s_last == GRID - 1) {
        __threadfence();
        __shared__ double sd[256];
        double a = 0.0;
        const float4* lf = (const float4*)d_loss;
        for (int i = t; i < BB / 4; i += 256) {
            float4 v = __ldcg(lf + i);
            a += (double)v.x + (double)v.y + (double)v.z + (double)v.w;
        }
        sd[t] = a;
        __syncthreads();
        for (int o = 128; o; o >>= 1) {
            if (t < o) sd[t] += sd[t + o];
            __syncthreads();
        }
        if (t == 0) {
            float L = (float)(sd[0] / (double)BB);
            if (osz >= nbig + BB + 1)      out[(size_t)nbig + BB] = L;
            else if (osz == 1)             out[0] = L;
            d_ticket = 0u;
        }
        // zero d_first2/d_cnt for the next replay (all blocks already past
        // their reads: every block incremented d_ticket after its last row)
        for (int k = t; k < CC; k += 256) { d_first2[k] = 0; d_cnt[k] = 0; }
    }
}

// ---------------- launch ----------------
extern "C" void kernel_launch(void* const* d_in, const int* in_sizes, int n_in,
                              void* d_out, int out_size) {
    const float* logits = (const float*)d_in[0];
    const void*  labels = d_in[1];
    float* out = (float*)d_out;
    long long osz = (long long)out_size;

    k1<<<64, 256>>>(labels);
    k2<<<9, 1024>>>();
    k_main<<<GRID, 256>>>(logits, out, osz);
}

// round 13
// speedup vs baseline: 1.2179x; 1.2179x over previous
#include <cuda_runtime.h>
#include <math.h>

#define BB 16384
#define CC 8192

// ---------------- device scratch (no runtime allocation) ----------------
// d_first2/d_cnt are ZERO when idle; k_main's final block re-zeroes them for
// the next graph replay. d_first2[lab] = max over rows i with label lab of
// (BB - i)  =>  first occurrence = BB - d_first2[lab]; 0 = label absent.
__device__ int   d_first2[CC];
__device__ int   d_cnt[CC];
__device__ int   d_hist[64 * CC];      // per-256-row-block histograms -> excl. block prefix
__device__ int   d_start[BB];          // excl. scan of group sizes (keyed by first-occ row)
__device__ int   d_rank[BB];           // stable rank within 256-row block (same label)
__device__ int   d_lab[BB];            // normalized int32 labels
__device__ float d_loss[BB];           // per-row loss
__device__ unsigned int d_ticket;      // last-block election in k_main

// ================= k1: detect + convert + count + stable in-block rank =================
__global__ void __launch_bounds__(256) k1(const void* __restrict__ labels) {
    const int t = threadIdx.x, b = blockIdx.x;
    __shared__ unsigned short srun[CC];   // 16KB running block histogram
    __shared__ int s_is64;

    // label width detection: int64 (LE) => all odd 32-bit words zero.
    // p < 8192 keeps word index valid for the int32 case too.
    {
        const int* w = (const int*)labels;
        int p = (b & 31) * 256 + t;
        int any = __syncthreads_or(w[2 * p + 1] != 0);
        if (t == 0) s_is64 = !any;
    }
    for (int k = t; k < CC; k += 256) srun[k] = 0;
    __syncthreads();

    const int i = b * 256 + t;
    const int lab = s_is64 ? (int)((const long long*)labels)[i]
                           : ((const int*)labels)[i];
    d_lab[i] = lab;
    atomicMax(&d_first2[lab], BB - i);     // zero-init friendly "first occurrence"
    atomicAdd(&d_cnt[lab], 1);

    // stable in-block rank via warp-ordered phases (u16 smem, no atomics)
    const int l = t & 31, w = t >> 5;
    unsigned eq = 0u;
#pragma unroll
    for (int j = 0; j < 32; j++) {
        int lj = __shfl_sync(0xffffffffu, lab, j);
        eq |= (unsigned)(lj == lab) << j;
    }
    const int before  = __popc(eq & ((1u << l) - 1u));
    const int total   = __popc(eq);
    const bool is_last = (31 - __clz(eq)) == l;
    int rank = 0;
    for (int ph = 0; ph < 8; ph++) {
        if (w == ph) {
            rank = (int)srun[lab] + before;
            __syncwarp();
            if (is_last) srun[lab] = (unsigned short)((int)srun[lab] + total);
        }
        __syncthreads();
    }
    d_rank[i] = rank;
    for (int k = t; k < CC; k += 256) d_hist[b * CC + k] = (int)srun[k];
}

// ================= k2: coalesced hist prefix (blocks 0-7) + group scan (block 8) =================
__global__ void __launch_bounds__(1024) k2() {
    const int t = threadIdx.x, b = blockIdx.x;
    if (b < 8) {
        // in-place exclusive prefix along the 64-block axis, one thread per
        // label column: consecutive threads -> consecutive addresses (coalesced)
        const int c = b * 1024 + t;
        int run = 0;
#pragma unroll 4
        for (int k = 0; k < 64; k++) {
            int v = d_hist[k * CC + c];
            d_hist[k * CC + c] = run;
            run += v;
        }
    } else {
        // exclusive scan of group sizes keyed by first-occurrence row
        __shared__ int sums[1024];
        const int base = t * 16;
        int local[16];
        int acc = 0;
#pragma unroll
        for (int k = 0; k < 16; k++) {
            int r = base + k;
            int lab = d_lab[r];
            int gv = (BB - d_first2[lab] == r) ? d_cnt[lab] : 0;
            local[k] = acc;
            acc += gv;
        }
        sums[t] = acc;
        __syncthreads();
        for (int off = 1; off < 1024; off <<= 1) {
            int v = (t >= off) ? sums[t - off] : 0;
            __syncthreads();
            sums[t] += v;
            __syncthreads();
        }
        int offset = (t == 0) ? 0 : sums[t - 1];
#pragma unroll
        for (int k = 0; k < 16; k++) d_start[base + k] = offset + local[k];
    }
}

// ================= main streaming kernel (R10 body, single-barrier reduce) =================
__global__ void __launch_bounds__(256) k_main(const float* __restrict__ logits,
                                              float* __restrict__ out,
                                              long long osz) {
    const int row = blockIdx.x;
    const int t = threadIdx.x;
    const int lab = d_lab[row];
    const int dst = d_start[BB - d_first2[lab]]
                  + d_hist[(row >> 8) * CC + lab] + d_rank[row];
    const float4* __restrict__ src = (const float4*)(logits + (size_t)row * CC);
    float4* __restrict__ o4 = (float4*)(out + (size_t)dst * CC);

    const int tgt4 = lab >> 2, tsub = lab & 3;
    const long long nbig = (long long)BB * CC;
    const bool do_store = (osz >= nbig);

    float s0 = 0.0f, s1 = 0.0f;
    float tval = 0.0f;
    bool have_t = false;

#pragma unroll
    for (int k = 0; k < 8; k++) {
        const int idx = k * 256 + t;
        float4 x = __ldcs(src + idx);
        if (idx == tgt4) {
            float vv = (tsub == 0) ? x.x : (tsub == 1) ? x.y : (tsub == 2) ? x.z : x.w;
            float nv = (vv > 0.0f) ? (vv / 2.00001f - 0.2f) : (vv * 2.00001f - 0.2f);
            if (tsub == 0) x.x = nv; else if (tsub == 1) x.y = nv;
            else if (tsub == 2) x.z = nv; else x.w = nv;
            tval = nv; have_t = true;
        }
        if (do_store) __stcs(o4 + idx, x);
        s0 += __expf(x.x) + __expf(x.y);
        s1 += __expf(x.z) + __expf(x.w);
    }

    // single-barrier block reduction: warp partials -> smem -> every thread sums 8
    __shared__ float red[8];
    float ws = s0 + s1;
#pragma unroll
    for (int o = 16; o; o >>= 1) ws += __shfl_xor_sync(0xffffffffu, ws, o);
    if ((t & 31) == 0) red[t >> 5] = ws;
    __syncthreads();
    const float s = ((red[0] + red[1]) + (red[2] + red[3]))
                  + ((red[4] + red[5]) + (red[6] + red[7]));

    if (have_t) {
        d_loss[row] = __logf(s) - tval;
        __threadfence();                       // publish loss before ticket
    }
    if (t == 0 && osz >= nbig + BB) out[(size_t)nbig + dst] = (float)lab;

    // ---- last block: deterministic loss reduction + scratch reset for next replay ----
    __shared__ unsigned int s_last;
    __syncthreads();
    if (t == 0) s_last = atomicAdd(&d_ticket, 1u);
    __syncthreads();
    if (s_last == BB - 1) {
        __threadfence();
        __shared__ double sd[256];
        double a = 0.0;
        const float4* lf = (const float4*)d_loss;
        for (int i = t; i < BB / 4; i += 256) {
            float4 v = __ldcg(lf + i);
            a += (double)v.x + (double)v.y + (double)v.z + (double)v.w;
        }
        sd[t] = a;
        __syncthreads();
        for (int o = 128; o; o >>= 1) {
            if (t < o) sd[t] += sd[t + o];
            __syncthreads();
        }
        if (t == 0) {
            float L = (float)(sd[0] / (double)BB);
            if (osz >= nbig + BB + 1)      out[(size_t)nbig + BB] = L;
            else if (osz == 1)             out[0] = L;
            d_ticket = 0u;
        }
        // zero d_first2/d_cnt for the next replay (all blocks already past
        // their reads: every block incremented d_ticket after computing dst)
        for (int k = t; k < CC; k += 256) { d_first2[k] = 0; d_cnt[k] = 0; }
    }
}

// ---------------- launch ----------------
extern "C" void kernel_launch(void* const* d_in, const int* in_sizes, int n_in,
                              void* d_out, int out_size) {
    const float* logits = (const float*)d_in[0];
    const void*  labels = d_in[1];
    float* out = (float*)d_out;
    long long osz = (long long)out_size;

    k1<<<64, 256>>>(labels);
    k2<<<9, 1024>>>();
    k_main<<<BB, 256>>>(logits, out, osz);
}

// round 14
// speedup vs baseline: 1.2768x; 1.0484x over previous
#include <cuda_runtime.h>
#include <math.h>

#define BB 16384
#define CC 8192

// ---------------- device scratch (no runtime allocation) ----------------
// d_first2/d_cnt are ZERO when idle; k_main's final block re-zeroes them for
// the next graph replay. d_first2[lab] = max over rows i with label lab of
// (BB - i)  =>  first occurrence = BB - d_first2[lab]; 0 = label absent.
__device__ int   d_first2[CC];
__device__ int   d_cnt[CC];
__device__ int   d_hist[64 * CC];      // per-256-row-block histograms -> excl. block prefix
__device__ int   d_start[BB];          // excl. scan of group sizes (keyed by first-occ row)
__device__ int   d_rank[BB];           // stable rank within 256-row block (same label)
__device__ int   d_lab[BB];            // normalized int32 labels
__device__ float d_loss[BB];           // per-row loss
__device__ unsigned int d_ticket;      // last-block election in k_main

// ================= k1: detect + convert + count + stable in-block rank =================
__global__ void __launch_bounds__(256) k1(const void* __restrict__ labels) {
    const int t = threadIdx.x, b = blockIdx.x;
    __shared__ unsigned short srun[CC];   // 16KB running block histogram
    __shared__ int s_is64;

    // label width detection: int64 (LE) => all odd 32-bit words zero.
    // p < 8192 keeps word index valid for the int32 case too.
    {
        const int* w = (const int*)labels;
        int p = (b & 31) * 256 + t;
        int any = __syncthreads_or(w[2 * p + 1] != 0);
        if (t == 0) s_is64 = !any;
    }
    // vectorized smem zero: 16KB as 1024 uint4
    {
        uint4* z = (uint4*)srun;
#pragma unroll
        for (int k = t; k < 1024; k += 256) z[k] = make_uint4(0u, 0u, 0u, 0u);
    }
    __syncthreads();

    const int i = b * 256 + t;
    const int lab = s_is64 ? (int)((const long long*)labels)[i]
                           : ((const int*)labels)[i];
    d_lab[i] = lab;
    atomicMax(&d_first2[lab], BB - i);     // zero-init friendly "first occurrence"
    atomicAdd(&d_cnt[lab], 1);

    // stable in-block rank via warp-ordered phases (u16 smem, no atomics)
    const int l = t & 31, w = t >> 5;
    unsigned eq = 0u;
#pragma unroll
    for (int j = 0; j < 32; j++) {
        int lj = __shfl_sync(0xffffffffu, lab, j);
        eq |= (unsigned)(lj == lab) << j;
    }
    const int before  = __popc(eq & ((1u << l) - 1u));
    const int total   = __popc(eq);
    const bool is_last = (31 - __clz(eq)) == l;
    int rank = 0;
    for (int ph = 0; ph < 8; ph++) {
        if (w == ph) {
            rank = (int)srun[lab] + before;
            __syncwarp();
            if (is_last) srun[lab] = (unsigned short)((int)srun[lab] + total);
        }
        __syncthreads();
    }
    d_rank[i] = rank;

    // vectorized hist writeout: u16 pairs -> int2 (8B coalesced stores)
    {
        const unsigned* sp = (const unsigned*)srun;      // 4096 packed pairs
        int2* hp = (int2*)(d_hist + b * CC);
#pragma unroll
        for (int k = t; k < 4096; k += 256) {
            unsigned v = sp[k];
            hp[k] = make_int2((int)(v & 0xffffu), (int)(v >> 16));
        }
    }
}

// ================= k2: coalesced hist prefix (blocks 0-7) + group scan (block 8) =================
__global__ void __launch_bounds__(1024) k2() {
    // PDL: allow k_main to launch early; its gridDependencySynchronize still
    // waits for this grid's completion before consuming prep data.
    cudaTriggerProgrammaticLaunchCompletion();

    const int t = threadIdx.x, b = blockIdx.x;
    if (b < 8) {
        // in-place exclusive prefix along the 64-block axis, one thread per
        // label column: consecutive threads -> consecutive addresses (coalesced)
        const int c = b * 1024 + t;
        int run = 0;
#pragma unroll 4
        for (int k = 0; k < 64; k++) {
            int v = d_hist[k * CC + c];
            d_hist[k * CC + c] = run;
            run += v;
        }
    } else {
        // exclusive scan of group sizes keyed by first-occurrence row
        __shared__ int sums[1024];
        const int base = t * 16;
        int local[16];
        int acc = 0;
#pragma unroll
        for (int k = 0; k < 16; k++) {
            int r = base + k;
            int lab = d_lab[r];
            int gv = (BB - d_first2[lab] == r) ? d_cnt[lab] : 0;
            local[k] = acc;
            acc += gv;
        }
        sums[t] = acc;
        __syncthreads();
        for (int off = 1; off < 1024; off <<= 1) {
            int v = (t >= off) ? sums[t - off] : 0;
            __syncthreads();
            sums[t] += v;
            __syncthreads();
        }
        int offset = (t == 0) ? 0 : sums[t - 1];
#pragma unroll
        for (int k = 0; k < 16; k++) d_start[base + k] = offset + local[k];
    }
}

// ================= main streaming kernel (proven body + pre-sync L2 prefetch) =================
__global__ void __launch_bounds__(256) k_main(const float* __restrict__ logits,
                                              float* __restrict__ out,
                                              long long osz) {
    const int row = blockIdx.x;
    const int t = threadIdx.x;
    const float* rowp = logits + (size_t)row * CC;

    // ---- pre-dependency prefetch: pull this block's row into L2 while the
    // prep kernels finish (early blocks) / ahead of the load loop (later ones).
    if ((t & 7) == 0) {
#pragma unroll
        for (int k = 0; k < 8; k++)
            asm volatile("prefetch.global.L2 [%0];" :: "l"(rowp + k * 1024 + t * 4));
    }
    cudaGridDependencySynchronize();

    const int lab = d_lab[row];
    const int dst = d_start[BB - d_first2[lab]]
                  + d_hist[(row >> 8) * CC + lab] + d_rank[row];
    const float4* __restrict__ src = (const float4*)rowp;
    float4* __restrict__ o4 = (float4*)(out + (size_t)dst * CC);

    const int tgt4 = lab >> 2, tsub = lab & 3;
    const long long nbig = (long long)BB * CC;
    const bool do_store = (osz >= nbig);

    float s0 = 0.0f, s1 = 0.0f;
    float tval = 0.0f;
    bool have_t = false;

#pragma unroll
    for (int k = 0; k < 8; k++) {
        const int idx = k * 256 + t;
        float4 x = __ldcs(src + idx);
        if (idx == tgt4) {
            float vv = (tsub == 0) ? x.x : (tsub == 1) ? x.y : (tsub == 2) ? x.z : x.w;
            float nv = (vv > 0.0f) ? (vv / 2.00001f - 0.2f) : (vv * 2.00001f - 0.2f);
            if (tsub == 0) x.x = nv; else if (tsub == 1) x.y = nv;
            else if (tsub == 2) x.z = nv; else x.w = nv;
            tval = nv; have_t = true;
        }
        if (do_store) __stcs(o4 + idx, x);
        s0 += __expf(x.x) + __expf(x.y);
        s1 += __expf(x.z) + __expf(x.w);
    }

    // single-barrier block reduction: warp partials -> smem -> every thread sums 8
    __shared__ float red[8];
    float ws = s0 + s1;
#pragma unroll
    for (int o = 16; o; o >>= 1) ws += __shfl_xor_sync(0xffffffffu, ws, o);
    if ((t & 31) == 0) red[t >> 5] = ws;
    __syncthreads();
    const float s = ((red[0] + red[1]) + (red[2] + red[3]))
                  + ((red[4] + red[5]) + (red[6] + red[7]));

    if (have_t) {
        d_loss[row] = __logf(s) - tval;
        __threadfence();                       // publish loss before ticket
    }
    if (t == 0 && osz >= nbig + BB) out[(size_t)nbig + dst] = (float)lab;

    // ---- last block: deterministic loss reduction + scratch reset for next replay ----
    __shared__ unsigned int s_last;
    __syncthreads();
    if (t == 0) s_last = atomicAdd(&d_ticket, 1u);
    __syncthreads();
    if (s_last == BB - 1) {
        __threadfence();
        __shared__ double sd[256];
        double a = 0.0;
        const float4* lf = (const float4*)d_loss;
        for (int i = t; i < BB / 4; i += 256) {
            float4 v = __ldcg(lf + i);
            a += (double)v.x + (double)v.y + (double)v.z + (double)v.w;
        }
        sd[t] = a;
        __syncthreads();
        for (int o = 128; o; o >>= 1) {
            if (t < o) sd[t] += sd[t + o];
            __syncthreads();
        }
        if (t == 0) {
            float L = (float)(sd[0] / (double)BB);
            if (osz >= nbig + BB + 1)      out[(size_t)nbig + BB] = L;
            else if (osz == 1)             out[0] = L;
            d_ticket = 0u;
        }
        // zero d_first2/d_cnt for the next replay (all blocks already past
        // their reads: every block incremented d_ticket after computing dst)
        for (int k = t; k < CC; k += 256) { d_first2[k] = 0; d_cnt[k] = 0; }
    }
}

// ---------------- launch ----------------
extern "C" void kernel_launch(void* const* d_in, const int* in_sizes, int n_in,
                              void* d_out, int out_size) {
    const float* logits = (const float*)d_in[0];
    const void*  labels = d_in[1];
    float* out = (float*)d_out;
    long long osz = (long long)out_size;

    k1<<<64, 256>>>(labels);
    k2<<<9, 1024>>>();

    cudaLaunchAttribute pdl[1];
    pdl[0].id = cudaLaunchAttributeProgrammaticStreamSerialization;
    pdl[0].val.programmaticStreamSerializationAllowed = 1;
    cudaLaunchConfig_t cfg = {};
    cfg.gridDim = dim3(BB);
    cfg.blockDim = dim3(256);
    cfg.dynamicSmemBytes = 0;
    cfg.stream = 0;
    cfg.attrs = pdl;
    cfg.numAttrs = 1;
    cudaLaunchKernelEx(&cfg, k_main, logits, out, osz);
}